// round 1
// baseline (speedup 1.0000x reference)
#include <cuda_runtime.h>
#include <cstdint>

// Problem dims
#define BATCH 32
#define SEQ   2048
#define DIN   256
#define HID   512
#define G4H   2048   // 4*HID
#define DOUT  256

// Recurrence kernel config: 128 CTAs, each owns 4 hidden units (512/128).
#define REC_CTAS    128
#define REC_THREADS 128
#define UNITS_PER_CTA 4
#define H_STRIDE 516          // 32-row h tile, padded: stride%32==4 -> conflict-free bcast
#define REC_SMEM_BYTES ((BATCH * H_STRIDE + HID * 16) * 4)

// Scratch (device globals: allocation-free, sanctioned by harness rules)
__device__ float g_xg[(size_t)SEQ * BATCH * G4H];    // [s][b][4H]  512 MB
__device__ float g_hall[(size_t)SEQ * BATCH * HID];  // [s][b][H]   128 MB
__device__ unsigned int g_bar;                        // monotonic grid barrier counter

// ---------------------------------------------------------------------------
// Generic tiled SGEMM: C = A(MxK) * B(KxN) (+bias), with output remapping.
// mode 0: A = x (param), store into g_xg with row r=(b*S+s) -> [s][b][col]
// mode 1: A = g_hall,    store into Cout with row r=(s*B+b) -> [b][s][col]
// ---------------------------------------------------------------------------
__global__ void __launch_bounds__(256)
sgemm64(const float* __restrict__ A, const float* __restrict__ Bm,
        const float* __restrict__ bias, float* __restrict__ Cout,
        int M, int N, int K, int mode)
{
    __shared__ float As[16][64 + 1];   // [k][m]
    __shared__ float Bs[16][64 + 4];   // [k][n]

    const float* __restrict__ Aeff = (mode == 1) ? g_hall : A;

    const int bm  = blockIdx.y * 64;
    const int bn  = blockIdx.x * 64;
    const int tid = threadIdx.x;
    const int tr  = tid >> 4;    // 0..15
    const int tc  = tid & 15;    // 0..15

    float acc[4][4];
#pragma unroll
    for (int i = 0; i < 4; ++i)
#pragma unroll
        for (int j = 0; j < 4; ++j) acc[i][j] = 0.f;

    for (int k0 = 0; k0 < K; k0 += 16) {
#pragma unroll
        for (int i = tid; i < 64 * 16; i += 256) {
            int m = i >> 4, k = i & 15;
            As[k][m] = Aeff[(size_t)(bm + m) * K + (k0 + k)];
        }
#pragma unroll
        for (int i = tid; i < 16 * 64; i += 256) {
            int k = i >> 6, n = i & 63;
            Bs[k][n] = Bm[(size_t)(k0 + k) * N + (bn + n)];
        }
        __syncthreads();
#pragma unroll
        for (int k = 0; k < 16; ++k) {
            float a0 = As[k][tr * 4 + 0];
            float a1 = As[k][tr * 4 + 1];
            float a2 = As[k][tr * 4 + 2];
            float a3 = As[k][tr * 4 + 3];
            float b0 = Bs[k][tc * 4 + 0];
            float b1 = Bs[k][tc * 4 + 1];
            float b2 = Bs[k][tc * 4 + 2];
            float b3 = Bs[k][tc * 4 + 3];
            acc[0][0] += a0 * b0; acc[0][1] += a0 * b1; acc[0][2] += a0 * b2; acc[0][3] += a0 * b3;
            acc[1][0] += a1 * b0; acc[1][1] += a1 * b1; acc[1][2] += a1 * b2; acc[1][3] += a1 * b3;
            acc[2][0] += a2 * b0; acc[2][1] += a2 * b1; acc[2][2] += a2 * b2; acc[2][3] += a2 * b3;
            acc[3][0] += a3 * b0; acc[3][1] += a3 * b1; acc[3][2] += a3 * b2; acc[3][3] += a3 * b3;
        }
        __syncthreads();
    }

#pragma unroll
    for (int i = 0; i < 4; ++i) {
        const int row = bm + tr * 4 + i;
#pragma unroll
        for (int j = 0; j < 4; ++j) {
            const int col = bn + tc * 4 + j;
            float v = acc[i][j] + (bias ? bias[col] : 0.f);
            if (mode == 0) {
                // row = b*SEQ + s  ->  g_xg[(s*BATCH + b)*G4H + col]
                int bb = row >> 11;         // / SEQ
                int s  = row & (SEQ - 1);
                g_xg[((size_t)s * BATCH + bb) * G4H + col] = v;
            } else {
                // row = s*BATCH + b -> Cout[(b*SEQ + s)*DOUT + col]
                int s  = row >> 5;          // / BATCH
                int bb = row & (BATCH - 1);
                Cout[((size_t)bb * SEQ + s) * DOUT + col] = v;
            }
        }
    }
}

// ---------------------------------------------------------------------------
// Persistent LSTM recurrence.
// 128 CTAs x 128 threads. CTA owns hidden units [cta*4, cta*4+4).
// thread t: b = t>>2 (batch), ul = t&3 (local unit). Each thread owns one
// (b, u) cell: keeps c in a register, computes all 4 gates.
// Wh slice (512x16 fp32, 32 KB) resident in SMEM; h broadcast via global+SMEM.
// Grid sync: monotonic counter barrier (reset by cudaMemsetAsync per launch).
// ---------------------------------------------------------------------------
__global__ void __launch_bounds__(REC_THREADS, 1)
lstm_rec_kernel(const float* __restrict__ Wh, const float* __restrict__ bias)
{
    extern __shared__ float sm[];
    float* h_sm = sm;                       // [32][H_STRIDE]
    float* w_sm = sm + BATCH * H_STRIDE;    // [512][16] = [k][ul*4+gate]

    const int tid = threadIdx.x;
    const int cta = blockIdx.x;
    const int u0  = cta * UNITS_PER_CTA;
    const int b   = tid >> 2;               // 0..31
    const int ul  = tid & 3;                // 0..3
    const int u   = u0 + ul;

    // Load Wh slice: w_sm[k*16 + lul*4 + g] = Wh[k][g*HID + u0 + lul]
    for (int idx = tid; idx < HID * 16; idx += REC_THREADS) {
        int k   = idx >> 4;
        int c   = idx & 15;
        int lul = c >> 2;
        int g   = c & 3;
        w_sm[idx] = Wh[(size_t)k * G4H + g * HID + u0 + lul];
    }

    const float bi = bias[0 * HID + u];
    const float bf = bias[1 * HID + u];
    const float bg = bias[2 * HID + u];
    const float bo = bias[3 * HID + u];

    float c_state = 0.f;
    __syncthreads();

    const float4* __restrict__ wrow = reinterpret_cast<const float4*>(w_sm) + ul;
    const float*  __restrict__ hrow = h_sm + b * H_STRIDE;

    for (int t = 0; t < SEQ; ++t) {
        float acc_i = 0.f, acc_f = 0.f, acc_g = 0.f, acc_o = 0.f;

        if (t > 0) {
            // Cooperative load of h_prev [32][512] (64 KB) into SMEM (L2 path)
            const float4* hp4 =
                reinterpret_cast<const float4*>(g_hall + (size_t)(t - 1) * BATCH * HID);
#pragma unroll 4
            for (int i = tid; i < BATCH * HID / 4; i += REC_THREADS) {
                float4 v = __ldcg(hp4 + i);
                int bb = i >> 7;              // (i*4)/512
                int kk = (i << 2) & (HID - 1);
                float* dst = h_sm + bb * H_STRIDE + kk;
                dst[0] = v.x; dst[1] = v.y; dst[2] = v.z; dst[3] = v.w;
            }
            __syncthreads();

#pragma unroll 8
            for (int k = 0; k < HID; ++k) {
                float  hv = hrow[k];
                float4 w  = wrow[k * 4];      // w_sm[k*16 + ul*4 .. +3]
                acc_i += w.x * hv;
                acc_f += w.y * hv;
                acc_g += w.z * hv;
                acc_o += w.w * hv;
            }
        }

        // Add precomputed input projection + bias
        const size_t xbase = ((size_t)t * BATCH + b) * G4H + u;
        acc_i += g_xg[xbase + 0 * HID] + bi;
        acc_f += g_xg[xbase + 1 * HID] + bf;
        acc_g += g_xg[xbase + 2 * HID] + bg;
        acc_o += g_xg[xbase + 3 * HID] + bo;

        // Gate math (flax order: i, f, g, o)
        float ig = 1.f / (1.f + __expf(-acc_i));
        float fg = 1.f / (1.f + __expf(-acc_f));
        float gg = tanhf(acc_g);
        float og = 1.f / (1.f + __expf(-acc_o));
        c_state  = fg * c_state + ig * gg;
        float hv = og * tanhf(c_state);

        g_hall[((size_t)t * BATCH + b) * HID + u] = hv;

        // Grid barrier (monotonic counter; also protects h_sm reuse)
        __syncthreads();
        if (tid == 0) {
            __threadfence();
            atomicAdd(&g_bar, 1u);
            const unsigned target = (unsigned)(t + 1) * (unsigned)REC_CTAS;
            while (*(volatile unsigned int*)&g_bar < target) {
                __nanosleep(100);
            }
            __threadfence();
        }
        __syncthreads();
    }
}

// ---------------------------------------------------------------------------
extern "C" void kernel_launch(void* const* d_in, const int* in_sizes, int n_in,
                              void* d_out, int out_size)
{
    const float* x    = (const float*)d_in[0];   // [B,S,D]
    const float* Wx   = (const float*)d_in[1];   // [D,4H]
    const float* Wh   = (const float*)d_in[2];   // [H,4H]
    const float* bias = (const float*)d_in[3];   // [4H]
    const float* Wo   = (const float*)d_in[4];   // [H,O]
    const float* bo   = (const float*)d_in[5];   // [O]
    float* y = (float*)d_out;                    // [B,S,O]

    (void)in_sizes; (void)n_in; (void)out_size;

    // Reset grid-barrier counter (graph-replay safe)
    void* barp = nullptr;
    cudaGetSymbolAddress(&barp, g_bar);
    cudaMemsetAsync(barp, 0, sizeof(unsigned int), 0);

    cudaFuncSetAttribute(lstm_rec_kernel,
                         cudaFuncAttributeMaxDynamicSharedMemorySize,
                         REC_SMEM_BYTES);

    // K1: xg = x @ Wx     (M=B*S=65536, N=4H=2048, K=D=256), no bias here
    {
        dim3 grid(G4H / 64, (BATCH * SEQ) / 64);
        sgemm64<<<grid, 256>>>(x, Wx, nullptr, nullptr,
                               BATCH * SEQ, G4H, DIN, 0);
    }

    // K2: persistent recurrence
    lstm_rec_kernel<<<REC_CTAS, REC_THREADS, REC_SMEM_BYTES>>>(Wh, bias);

    // K3: y = h_all @ Wo + bo  (M=S*B=65536, N=O=256, K=H=512)
    {
        dim3 grid(DOUT / 64, (BATCH * SEQ) / 64);
        sgemm64<<<grid, 256>>>(nullptr, Wo, bo, y,
                               SEQ * BATCH, DOUT, HID, 1);
    }
}

// round 2
// speedup vs baseline: 1.3699x; 1.3699x over previous
#include <cuda_runtime.h>
#include <cstdint>

// Problem dims
#define BATCH 32
#define SEQ   2048
#define DIN   256
#define HID   512
#define G4H   2048
#define DOUT  256

// Recurrence partition: 4 batch-groups x 32 unit-groups = 128 CTAs
#define R_CTAS    128
#define R_THREADS 256
#define NBG 4
#define BPG 8     // batches per group
#define UPG 16    // units per group
#define H_PAD 520 // padded h row stride (520 % 32 == 8 -> conflict-free)

#define W_FLOATS  (HID * UPG * 4)   // 32768 floats = 128 KB
#define H_FLOATS  (BPG * H_PAD)     // 4160 floats  = 16.6 KB
#define RED_U64   256               // 128 cells x 2 u64 partials
#define R_SMEM    ((W_FLOATS + H_FLOATS) * 4 + RED_U64 * 8)

// Scratch (device globals; allocation-free per harness rules)
__device__ float g_xg[(size_t)SEQ * BATCH * G4H];   // [s][b][u][4]  (gate-packed)
__device__ float g_hT[(size_t)SEQ * HID * BATCH];   // [s][u][b]     (transposed h)
__device__ unsigned g_bar[NBG * 32];                // per-group barrier counters (padded)

typedef unsigned long long u64;

// ---- packed f32x2 helpers (sm_100+) --------------------------------------
__device__ __forceinline__ u64 pack_dup(float x) {
    u64 r; asm("mov.b64 %0, {%1, %1};" : "=l"(r) : "f"(x)); return r;
}
__device__ __forceinline__ u64 ffma2(u64 a, u64 b, u64 c) {
    u64 d; asm("fma.rn.f32x2 %0, %1, %2, %3;" : "=l"(d) : "l"(a), "l"(b), "l"(c));
    return d;
}
__device__ __forceinline__ u64 fadd2(u64 a, u64 b) {
    u64 d; asm("add.rn.f32x2 %0, %1, %2;" : "=l"(d) : "l"(a), "l"(b)); return d;
}
__device__ __forceinline__ void unpack2(u64 v, float& lo, float& hi) {
    asm("mov.b64 {%0, %1}, %2;" : "=f"(lo), "=f"(hi) : "l"(v));
}
__device__ __forceinline__ unsigned ld_acq(const unsigned* p) {
    unsigned v; asm volatile("ld.acquire.gpu.global.u32 %0, [%1];" : "=r"(v) : "l"(p));
    return v;
}
__device__ __forceinline__ void red_rel_add1(unsigned* p) {
    asm volatile("red.release.gpu.global.add.u32 [%0], 1;" :: "l"(p));
}

// ---------------------------------------------------------------------------
// Tiled SGEMM with f32x2-packed 4x4 microkernel (64x64 tile, Kt=16).
// mode 0 (K1): A = x [B,S,D] row r=b*S+s; out -> g_xg gate-packed [s][b][u][4]
// mode 1 (K3): A = g_hT [s][u][b] row r=s*B+b; out -> y[b][s][col] (+bias)
// ---------------------------------------------------------------------------
__global__ void __launch_bounds__(256)
sgemm64(const float* __restrict__ A, const float* __restrict__ Bm,
        const float* __restrict__ bias, float* __restrict__ Cout,
        int M, int N, int K, int mode)
{
    __shared__ __align__(16) float As[16 * 68];
    __shared__ __align__(16) float Bs[16 * 68];

    const int bm  = blockIdx.y * 64;
    const int bn  = blockIdx.x * 64;
    const int tid = threadIdx.x;
    const int tr  = tid >> 4;
    const int tc  = tid & 15;

    u64 acc[4][2];
#pragma unroll
    for (int i = 0; i < 4; ++i) { acc[i][0] = 0ull; acc[i][1] = 0ull; }

    for (int k0 = 0; k0 < K; k0 += 16) {
        if (mode == 0) {
#pragma unroll
            for (int i = tid; i < 64 * 16; i += 256) {
                int m = i >> 4, k = i & 15;
                As[k * 68 + m] = A[(size_t)(bm + m) * K + (k0 + k)];
            }
        } else {
            // A[r][k] = g_hT[s*HID*BATCH + k*BATCH + b], r = s*32+b (m-inner: coalesced)
#pragma unroll
            for (int i = tid; i < 16 * 64; i += 256) {
                int k = i >> 6, m = i & 63;
                int row = bm + m;
                int s = row >> 5, b = row & 31;
                As[k * 68 + m] = g_hT[(size_t)s * (HID * BATCH) + (k0 + k) * BATCH + b];
            }
        }
#pragma unroll
        for (int i = tid; i < 16 * 64; i += 256) {
            int k = i >> 6, n = i & 63;
            Bs[k * 68 + n] = Bm[(size_t)(k0 + k) * N + (bn + n)];
        }
        __syncthreads();
#pragma unroll
        for (int k = 0; k < 16; ++k) {
            float4 a = *(const float4*)&As[k * 68 + tr * 4];
            ulonglong2 b = *(const ulonglong2*)&Bs[k * 68 + tc * 4];
            u64 a0 = pack_dup(a.x), a1 = pack_dup(a.y);
            u64 a2 = pack_dup(a.z), a3 = pack_dup(a.w);
            acc[0][0] = ffma2(a0, b.x, acc[0][0]); acc[0][1] = ffma2(a0, b.y, acc[0][1]);
            acc[1][0] = ffma2(a1, b.x, acc[1][0]); acc[1][1] = ffma2(a1, b.y, acc[1][1]);
            acc[2][0] = ffma2(a2, b.x, acc[2][0]); acc[2][1] = ffma2(a2, b.y, acc[2][1]);
            acc[3][0] = ffma2(a3, b.x, acc[3][0]); acc[3][1] = ffma2(a3, b.y, acc[3][1]);
        }
        __syncthreads();
    }

#pragma unroll
    for (int i = 0; i < 4; ++i) {
        const int row = bm + tr * 4 + i;
        float v[4];
        unpack2(acc[i][0], v[0], v[1]);
        unpack2(acc[i][1], v[2], v[3]);
#pragma unroll
        for (int j = 0; j < 4; ++j) {
            const int col = bn + tc * 4 + j;
            float val = v[j] + (bias ? bias[col] : 0.f);
            if (mode == 0) {
                // row = b*SEQ+s ; col = g*HID+u -> g_xg[((s*32+b)*512+u)*4+g]
                int bb = row >> 11;
                int s  = row & (SEQ - 1);
                int u  = col & (HID - 1);
                int g  = col >> 9;
                g_xg[(((size_t)s * BATCH + bb) * HID + u) * 4 + g] = val;
            } else {
                // row = s*BATCH+b -> y[(b*SEQ+s)*DOUT+col]
                int s  = row >> 5;
                int bb = row & (BATCH - 1);
                Cout[((size_t)bb * SEQ + s) * DOUT + col] = val;
            }
        }
    }
}

// ---------------------------------------------------------------------------
// Persistent LSTM recurrence.
// CTA = (bg, ug): owns batches [bg*8,bg*8+8) x units [ug*16,ug*16+16).
// 256 threads: kq = tid>>7 (k half), r = tid&127: b_l = r>>4, u_l = r&15.
// Inner loop: packed gate pairs, 5 instr / 8 FMA. Barrier per batch-group.
// ---------------------------------------------------------------------------
__global__ void __launch_bounds__(R_THREADS, 1)
lstm_rec_kernel(const float* __restrict__ Wh, const float* __restrict__ bias)
{
    extern __shared__ __align__(16) float sm[];
    float* w_sm = sm;                       // [512][16][4]  (k, u_l, gate)
    float* h_sm = sm + W_FLOATS;            // [8][H_PAD]    (b_l, k)
    u64*   red  = (u64*)(sm + W_FLOATS + H_FLOATS);  // [128][2]

    const int tid = threadIdx.x;
    const int cta = blockIdx.x;
    const int bg  = cta >> 5;               // 0..3
    const int ug  = cta & 31;               // 0..31
    const int kq  = tid >> 7;               // 0,1
    const int r   = tid & 127;
    const int b_l = r >> 4;                 // 0..7
    const int u_l = r & 15;                 // 0..15
    const int u0  = ug * UPG;
    const int b   = bg * BPG + b_l;
    const int u   = u0 + u_l;

    unsigned* ctr = &g_bar[bg * 32];

    // Load Wh slice: w_sm[k*64 + u_l*4 + g] = Wh[k][g*512 + u0+u_l]
    for (int idx = tid; idx < W_FLOATS; idx += R_THREADS) {
        int k   = idx >> 6;
        int rem = idx & 63;
        int lu  = rem >> 2;
        int g   = rem & 3;
        w_sm[idx] = Wh[(size_t)k * G4H + g * HID + u0 + lu];
    }

    float bi = 0.f, bf = 0.f, bgv = 0.f, bo = 0.f;
    if (kq == 0) {
        bi  = bias[0 * HID + u];
        bf  = bias[1 * HID + u];
        bgv = bias[2 * HID + u];
        bo  = bias[3 * HID + u];
    }

    float c_state = 0.f;
    __syncthreads();

    const float* hr = h_sm + b_l * H_PAD + kq * 256;
    const ulonglong2* wr = (const ulonglong2*)w_sm + (kq * 256 * 16 + u_l);
    const float4* xg4p = (const float4*)g_xg;  // index: (s*32+b)*512 + u

    for (int t = 0; t < SEQ; ++t) {
        // Prefetch input-projection gates (independent of barrier)
        float4 xg = make_float4(0.f, 0.f, 0.f, 0.f);
        if (kq == 0)
            xg = __ldcg(xg4p + ((size_t)t * BATCH + b) * HID + u);

        u64 acc_if = 0ull, acc_go = 0ull;

        if (t > 0) {
            // Wait for all 32 CTAs of this batch-group to finish step t-1
            if (tid == 0) {
                while (ld_acq(ctr) < (unsigned)(t * 32)) { }
            }
            __syncthreads();

            // Fill h_sm[b_l][k] from g_hT[t-1][k][bg*8 .. +8] (16 KB, contiguous sectors)
            {
                const float* src = g_hT + (size_t)(t - 1) * (HID * BATCH) + bg * BPG;
                int uu = tid * 2;
#pragma unroll
                for (int d = 0; d < 2; ++d) {
                    int k = uu + d;
                    float4 v0 = __ldcg((const float4*)(src + (size_t)k * BATCH));
                    float4 v1 = __ldcg((const float4*)(src + (size_t)k * BATCH + 4));
                    h_sm[0 * H_PAD + k] = v0.x;
                    h_sm[1 * H_PAD + k] = v0.y;
                    h_sm[2 * H_PAD + k] = v0.z;
                    h_sm[3 * H_PAD + k] = v0.w;
                    h_sm[4 * H_PAD + k] = v1.x;
                    h_sm[5 * H_PAD + k] = v1.y;
                    h_sm[6 * H_PAD + k] = v1.z;
                    h_sm[7 * H_PAD + k] = v1.w;
                }
            }
            __syncthreads();

            // Recurrent GEMM slice: 256 k per thread, gate pairs packed
#pragma unroll 8
            for (int k = 0; k < 256; ++k) {
                u64 h2 = pack_dup(hr[k]);
                ulonglong2 w = wr[(size_t)k * 16];
                acc_if = ffma2(w.x, h2, acc_if);
                acc_go = ffma2(w.y, h2, acc_go);
            }
        }

        // Cross-half reduction via SMEM
        if (kq == 1) {
            red[r * 2 + 0] = acc_if;
            red[r * 2 + 1] = acc_go;
        }
        __syncthreads();

        if (kq == 0) {
            acc_if = fadd2(acc_if, red[r * 2 + 0]);
            acc_go = fadd2(acc_go, red[r * 2 + 1]);

            float ai, af, ag, ao;
            unpack2(acc_if, ai, af);
            unpack2(acc_go, ag, ao);
            ai += xg.x + bi;
            af += xg.y + bf;
            ag += xg.z + bgv;
            ao += xg.w + bo;

            float ig = 1.f / (1.f + __expf(-ai));
            float fg = 1.f / (1.f + __expf(-af));
            float gg = tanhf(ag);
            float og = 1.f / (1.f + __expf(-ao));
            c_state  = fg * c_state + ig * gg;
            float hv = og * tanhf(c_state);

            g_hT[(size_t)t * (HID * BATCH) + (size_t)u * BATCH + b] = hv;
        }

        __syncthreads();             // all h stores ordered before arrival
        if (tid == 0) red_rel_add1(ctr);
    }
}

// ---------------------------------------------------------------------------
extern "C" void kernel_launch(void* const* d_in, const int* in_sizes, int n_in,
                              void* d_out, int out_size)
{
    const float* x    = (const float*)d_in[0];   // [B,S,D]
    const float* Wx   = (const float*)d_in[1];   // [D,4H]
    const float* Wh   = (const float*)d_in[2];   // [H,4H]
    const float* bias = (const float*)d_in[3];   // [4H]
    const float* Wo   = (const float*)d_in[4];   // [H,O]
    const float* bo   = (const float*)d_in[5];   // [O]
    float* y = (float*)d_out;                    // [B,S,O]

    (void)in_sizes; (void)n_in; (void)out_size;

    // Reset barrier counters (graph-capturable async memset)
    void* barp = nullptr;
    cudaGetSymbolAddress(&barp, g_bar);
    cudaMemsetAsync(barp, 0, NBG * 32 * sizeof(unsigned), 0);

    cudaFuncSetAttribute(lstm_rec_kernel,
                         cudaFuncAttributeMaxDynamicSharedMemorySize, R_SMEM);

    // K1: xg = x @ Wx  (M=65536, N=2048, K=256) -> g_xg gate-packed
    {
        dim3 grid(G4H / 64, (BATCH * SEQ) / 64);
        sgemm64<<<grid, 256>>>(x, Wx, nullptr, nullptr,
                               BATCH * SEQ, G4H, DIN, 0);
    }

    // K2: persistent recurrence
    lstm_rec_kernel<<<R_CTAS, R_THREADS, R_SMEM>>>(Wh, bias);

    // K3: y = h @ Wo + bo  (M=65536, N=256, K=512), A from g_hT
    {
        dim3 grid(DOUT / 64, (BATCH * SEQ) / 64);
        sgemm64<<<grid, 256>>>(nullptr, Wo, bo, y,
                               SEQ * BATCH, DOUT, HID, 1);
    }
}

// round 3
// speedup vs baseline: 1.8391x; 1.3425x over previous
#include <cuda_runtime.h>
#include <cstdint>

// Problem dims
#define BATCH 32
#define SEQ   2048
#define DIN   256
#define HID   512
#define G4H   2048
#define DOUT  256

// Recurrence: 4 batch-groups x 32 unit-groups = 128 CTAs, 512 threads each
#define NBG       4
#define R_CTAS    128
#define R_THREADS 512
#define UPG       16
#define R_SMEM    ((512*8 + 16*256) * 8)   // h_dup + partials, 64 KB

// Scratch (device globals; allocation-free per harness rules)
__device__ float g_xg[(size_t)SEQ * BATCH * G4H];   // [s][b][g*512+u] (bias folded in)
__device__ float g_hT[(size_t)SEQ * HID * BATCH];   // [s][u][b]
__device__ unsigned g_bar[NBG * 32];                // per-group monotonic counters

typedef unsigned long long u64;

// ---- packed f32x2 helpers (sm_100+) --------------------------------------
__device__ __forceinline__ u64 pack_dup(float x) {
    u64 r; asm("mov.b64 %0, {%1, %1};" : "=l"(r) : "f"(x)); return r;
}
__device__ __forceinline__ u64 pack2(float lo, float hi) {
    u64 r; asm("mov.b64 %0, {%1, %2};" : "=l"(r) : "f"(lo), "f"(hi)); return r;
}
__device__ __forceinline__ u64 ffma2(u64 a, u64 b, u64 c) {
    u64 d; asm("fma.rn.f32x2 %0, %1, %2, %3;" : "=l"(d) : "l"(a), "l"(b), "l"(c));
    return d;
}
__device__ __forceinline__ u64 fadd2(u64 a, u64 b) {
    u64 d; asm("add.rn.f32x2 %0, %1, %2;" : "=l"(d) : "l"(a), "l"(b)); return d;
}
__device__ __forceinline__ void unpack2(u64 v, float& lo, float& hi) {
    asm("mov.b64 {%0, %1}, %2;" : "=f"(lo), "=f"(hi) : "l"(v));
}
__device__ __forceinline__ unsigned ld_acq(const unsigned* p) {
    unsigned v; asm volatile("ld.acquire.gpu.global.u32 %0, [%1];" : "=r"(v) : "l"(p));
    return v;
}
__device__ __forceinline__ void red_rel_add1(unsigned* p) {
    asm volatile("red.release.gpu.global.add.u32 [%0], 1;" :: "l"(p));
}

// ---------------------------------------------------------------------------
// Tiled SGEMM (64x64 tile, Kt=32) with f32x2 microkernel.
// mode 0 (K1): A = x [B,S,D], row r=b*S+s; out -> g_xg[s][b][col] (+bias)
// mode 1 (K3): A = g_hT [s][u][b], row r=s*B+b; out -> y[b][s][col] (+bias)
// ---------------------------------------------------------------------------
__global__ void __launch_bounds__(256)
sgemm64(const float* __restrict__ A, const float* __restrict__ Bm,
        const float* __restrict__ bias, float* __restrict__ Cout,
        int M, int N, int K, int mode)
{
    __shared__ __align__(16) float As[32 * 68];
    __shared__ __align__(16) float Bs[32 * 68];

    const int bm  = blockIdx.y * 64;
    const int bn  = blockIdx.x * 64;
    const int tid = threadIdx.x;
    const int tr  = tid >> 4;
    const int tc  = tid & 15;

    u64 acc[4][2];
#pragma unroll
    for (int i = 0; i < 4; ++i) { acc[i][0] = 0ull; acc[i][1] = 0ull; }

    for (int k0 = 0; k0 < K; k0 += 32) {
        if (mode == 0) {
#pragma unroll
            for (int j = 0; j < 8; ++j) {
                int i = tid + j * 256;
                int m = i >> 5, kk = i & 31;
                As[kk * 68 + m] = A[(size_t)(bm + m) * K + (k0 + kk)];
            }
        } else {
#pragma unroll
            for (int j = 0; j < 8; ++j) {
                int i = tid + j * 256;
                int kk = i >> 6, m = i & 63;
                int row = bm + m;
                int s = row >> 5, b = row & 31;
                As[kk * 68 + m] = g_hT[(size_t)s * (HID * BATCH) + (size_t)(k0 + kk) * BATCH + b];
            }
        }
#pragma unroll
        for (int j = 0; j < 8; ++j) {
            int i = tid + j * 256;
            int kk = i >> 6, n = i & 63;
            Bs[kk * 68 + n] = Bm[(size_t)(k0 + kk) * N + (bn + n)];
        }
        __syncthreads();
#pragma unroll
        for (int kk = 0; kk < 32; ++kk) {
            float4 a = *(const float4*)&As[kk * 68 + tr * 4];
            ulonglong2 b = *(const ulonglong2*)&Bs[kk * 68 + tc * 4];
            u64 a0 = pack_dup(a.x), a1 = pack_dup(a.y);
            u64 a2 = pack_dup(a.z), a3 = pack_dup(a.w);
            acc[0][0] = ffma2(a0, b.x, acc[0][0]); acc[0][1] = ffma2(a0, b.y, acc[0][1]);
            acc[1][0] = ffma2(a1, b.x, acc[1][0]); acc[1][1] = ffma2(a1, b.y, acc[1][1]);
            acc[2][0] = ffma2(a2, b.x, acc[2][0]); acc[2][1] = ffma2(a2, b.y, acc[2][1]);
            acc[3][0] = ffma2(a3, b.x, acc[3][0]); acc[3][1] = ffma2(a3, b.y, acc[3][1]);
        }
        __syncthreads();
    }

#pragma unroll
    for (int i = 0; i < 4; ++i) {
        const int row = bm + tr * 4 + i;
        float4 v;
        unpack2(acc[i][0], v.x, v.y);
        unpack2(acc[i][1], v.z, v.w);
        const int col0 = bn + tc * 4;
        v.x += bias[col0 + 0];
        v.y += bias[col0 + 1];
        v.z += bias[col0 + 2];
        v.w += bias[col0 + 3];
        if (mode == 0) {
            int bb = row >> 11;           // / SEQ
            int s  = row & (SEQ - 1);
            *(float4*)&g_xg[((size_t)s * BATCH + bb) * G4H + col0] = v;
        } else {
            int s  = row >> 5;            // / BATCH
            int bb = row & (BATCH - 1);
            *(float4*)&Cout[((size_t)bb * SEQ + s) * DOUT + col0] = v;
        }
    }
}

// ---------------------------------------------------------------------------
// Persistent LSTM recurrence — weights in REGISTERS, h broadcast from SMEM.
// CTA (bg, ug): batches [bg*8, bg*8+8), units [ug*16, ug*16+16).
// Compute thread (kc = tid>>5, cp = tid&31): owns k-chunk kc*32..+32 and
//   gate-pair cp -> (u_l = cp>>1, p = cp&1; p0 = gates(i,f), p1 = (g,o)).
//   Holds 32 packed f32x2 Wh values in registers. Inner loop: warp-uniform
//   LDS.128 of duplicated h (1-cycle broadcast) + FFMA2 only.
// Gate thread (tid<128): (u_g = tid>>3, b_g = tid&7) reduces 16 k-chunk
//   partials, does gate math, stores h, releases the group barrier.
// ---------------------------------------------------------------------------
__global__ void __launch_bounds__(R_THREADS, 1)
lstm_rec_kernel(const float* __restrict__ Wh)
{
    extern __shared__ __align__(16) u64 sm[];
    u64* h_dup = sm;             // [512][8]   dup'd h: {h,h} per (k, b)
    u64* part  = sm + 512 * 8;   // [kc=16][p=2][u=16][b=8]

    const int tid = threadIdx.x;
    const int bg  = blockIdx.x >> 5;
    const int ug  = blockIdx.x & 31;
    const int kc  = tid >> 5;
    const int cp  = tid & 31;
    const int u_l = cp >> 1;
    const int p   = cp & 1;

    unsigned* ctr = &g_bar[bg * 32];

    // Load this thread's Wh slice into registers (one-time).
    u64 w[32];
    {
        const float* w0 = Wh + (size_t)(kc * 32) * G4H + (2 * p) * HID + ug * UPG + u_l;
#pragma unroll
        for (int i = 0; i < 32; ++i)
            w[i] = pack2(w0[(size_t)i * G4H], w0[(size_t)i * G4H + HID]);
    }

    const int u_g = tid >> 3;    // gate-thread coords (valid tid<128)
    const int b_g = tid & 7;
    float c_state = 0.f;

    for (int t = 0; t < SEQ; ++t) {
        // Prefetch input projection (bias already folded in by K1)
        float xi = 0.f, xf = 0.f, xgv = 0.f, xo = 0.f;
        if (tid < 128) {
            const float* xp = g_xg + ((size_t)t * BATCH + bg * 8 + b_g) * G4H + ug * UPG + u_g;
            xi  = __ldcg(xp + 0 * HID);
            xf  = __ldcg(xp + 1 * HID);
            xgv = __ldcg(xp + 2 * HID);
            xo  = __ldcg(xp + 3 * HID);
        }

        if (t > 0) {
            if (tid == 0) {
                while (ld_acq(ctr) < (unsigned)(t * 32)) { }
            }
            __syncthreads();   // S1: barrier seen; also fences h_dup/part reuse

            // Fill duplicated h: thread handles k = tid
            {
                const float* src = g_hT + (size_t)(t - 1) * (HID * BATCH)
                                        + (size_t)tid * BATCH + bg * 8;
                float4 v0 = __ldcg((const float4*)src);
                float4 v1 = __ldcg((const float4*)(src + 4));
                u64* d = h_dup + tid * 8;
                d[0] = pack_dup(v0.x); d[1] = pack_dup(v0.y);
                d[2] = pack_dup(v0.z); d[3] = pack_dup(v0.w);
                d[4] = pack_dup(v1.x); d[5] = pack_dup(v1.y);
                d[6] = pack_dup(v1.z); d[7] = pack_dup(v1.w);
            }
            __syncthreads();   // S2

            // Outer-product mainloop: w in regs, h warp-uniform broadcast
            u64 a0 = 0, a1 = 0, a2 = 0, a3 = 0, a4 = 0, a5 = 0, a6 = 0, a7 = 0;
            const ulonglong2* h4 = (const ulonglong2*)(h_dup + (size_t)kc * 32 * 8);
#pragma unroll
            for (int i = 0; i < 32; ++i) {
                ulonglong2 ha = h4[i * 4 + 0];
                ulonglong2 hb = h4[i * 4 + 1];
                ulonglong2 hc = h4[i * 4 + 2];
                ulonglong2 hd = h4[i * 4 + 3];
                u64 wi = w[i];
                a0 = ffma2(wi, ha.x, a0); a1 = ffma2(wi, ha.y, a1);
                a2 = ffma2(wi, hb.x, a2); a3 = ffma2(wi, hb.y, a3);
                a4 = ffma2(wi, hc.x, a4); a5 = ffma2(wi, hc.y, a5);
                a6 = ffma2(wi, hd.x, a6); a7 = ffma2(wi, hd.y, a7);
            }
            ulonglong2* pp = (ulonglong2*)(part + ((size_t)kc * 256 + p * 128 + u_l * 8));
            pp[0] = make_ulonglong2(a0, a1);
            pp[1] = make_ulonglong2(a2, a3);
            pp[2] = make_ulonglong2(a4, a5);
            pp[3] = make_ulonglong2(a6, a7);
        }
        __syncthreads();       // S3: partials visible

        if (tid < 128) {
            u64 s0 = 0ull, s1 = 0ull;
            if (t > 0) {
                const u64* q = part + (size_t)u_g * 8 + b_g;
#pragma unroll
                for (int kcc = 0; kcc < 16; ++kcc) {
                    s0 = fadd2(s0, q[kcc * 256]);        // p=0: (i,f)
                    s1 = fadd2(s1, q[kcc * 256 + 128]);  // p=1: (g,o)
                }
            }
            float ai, af, ag, ao;
            unpack2(s0, ai, af);
            unpack2(s1, ag, ao);
            ai += xi; af += xf; ag += xgv; ao += xo;

            float ig = 1.f / (1.f + __expf(-ai));
            float fg = 1.f / (1.f + __expf(-af));
            float gg = tanhf(ag);
            float og = 1.f / (1.f + __expf(-ao));
            c_state  = fg * c_state + ig * gg;
            float hv = og * tanhf(c_state);

            g_hT[(size_t)t * (HID * BATCH) + (size_t)(ug * UPG + u_g) * BATCH
                 + bg * 8 + b_g] = hv;

            // Order the 4 gate-warps' h stores, then release the group barrier
            asm volatile("bar.sync 1, 128;" ::: "memory");
            if (tid == 0) red_rel_add1(ctr);
        }
    }
}

// ---------------------------------------------------------------------------
extern "C" void kernel_launch(void* const* d_in, const int* in_sizes, int n_in,
                              void* d_out, int out_size)
{
    const float* x    = (const float*)d_in[0];   // [B,S,D]
    const float* Wx   = (const float*)d_in[1];   // [D,4H]
    const float* Wh   = (const float*)d_in[2];   // [H,4H]
    const float* bias = (const float*)d_in[3];   // [4H]
    const float* Wo   = (const float*)d_in[4];   // [H,O]
    const float* bo   = (const float*)d_in[5];   // [O]
    float* y = (float*)d_out;                    // [B,S,O]

    (void)in_sizes; (void)n_in; (void)out_size;

    // Reset barrier counters (graph-capturable async memset)
    void* barp = nullptr;
    cudaGetSymbolAddress(&barp, g_bar);
    cudaMemsetAsync(barp, 0, NBG * 32 * sizeof(unsigned), 0);

    cudaFuncSetAttribute(lstm_rec_kernel,
                         cudaFuncAttributeMaxDynamicSharedMemorySize, R_SMEM);

    // K1: xg = x @ Wx + b  (M=65536, N=2048, K=256) -> g_xg [s][b][col]
    {
        dim3 grid(G4H / 64, (BATCH * SEQ) / 64);
        sgemm64<<<grid, 256>>>(x, Wx, bias, nullptr,
                               BATCH * SEQ, G4H, DIN, 0);
    }

    // K2: persistent recurrence
    lstm_rec_kernel<<<R_CTAS, R_THREADS, R_SMEM>>>(Wh);

    // K3: y = h @ Wo + bo  (M=65536, N=256, K=512), A from g_hT
    {
        dim3 grid(DOUT / 64, (BATCH * SEQ) / 64);
        sgemm64<<<grid, 256>>>(nullptr, Wo, bo, y,
                               SEQ * BATCH, DOUT, HID, 1);
    }
}